// round 5
// baseline (speedup 1.0000x reference)
#include <cuda_runtime.h>
#include <cuda_bf16.h>
#include <math.h>

// ---------------------------------------------------------------------------
// Problem constants
// ---------------------------------------------------------------------------
#define BB 8
#define CIN0 3
#define HH 512
#define WW 512
#define TOPK 200
#define SCORE_T 0.01f
#define IOU_T 0.5f
#define GRID 32           // Gh = Gw = 32
#define NCELL (GRID*GRID) // 1024

// ---------------------------------------------------------------------------
// Scratch (static device arrays; no allocation allowed)
// ---------------------------------------------------------------------------
__device__ float g_x1[BB * 32  * 256 * 256];   // 64 MB
__device__ float g_x2[BB * 64  * 128 * 128];   // 32 MB
__device__ float g_x3[BB * 128 * 64  * 64 ];   // 16 MB
__device__ float g_x4[BB * 256 * 32  * 32 ];   //  8 MB
__device__ float g_pred[BB * 5 * NCELL];

// Kahan compensated add. __f*_rn intrinsics block reassociation/contraction.
__device__ __forceinline__ void kadd(float& s, float& c, float term) {
    float y = __fsub_rn(term, c);
    float t = __fadd_rn(s, y);
    c = __fsub_rn(__fsub_rn(t, s), y);
    s = t;
}

// ---------------------------------------------------------------------------
// Fused conv3x3(SAME) + bias + ReLU + maxpool2x2, Kahan-compensated fp32.
// Each thread computes one POOLED output pixel (max over 2x2 conv outputs).
// Block 16x16 -> pooled 16x16 tile -> 32x32 pre-pool region -> 34x34 input
// tile (halo 1) per input channel.
// ---------------------------------------------------------------------------
__global__ void conv_relu_pool_kernel(const float* __restrict__ in,
                                      const float* __restrict__ w,
                                      const float* __restrict__ bias,
                                      float* __restrict__ out,
                                      int CIN, int CO, int Hin, int Win) {
    const int Hp = Hin >> 1, Wp = Win >> 1;
    const int tx = threadIdx.x, ty = threadIdx.y;
    const int tileX = blockIdx.x * 16, tileY = blockIdx.y * 16;
    const int z  = blockIdx.z;
    const int co = z % CO;
    const int b  = z / CO;

    __shared__ float s[34][36];   // padded to soften bank conflicts

    const float* inb = in + (long long)b * CIN * Hin * Win;

    float s00 = 0.f, c00 = 0.f;
    float s01 = 0.f, c01 = 0.f;
    float s10 = 0.f, c10 = 0.f;
    float s11 = 0.f, c11 = 0.f;
    const int lx = 2 * tx;
    const int ly = 2 * ty;
    const int tid = ty * 16 + tx;

    for (int ci = 0; ci < CIN; ci++) {
        const float* ich = inb + (long long)ci * Hin * Win;
        for (int idx = tid; idx < 34 * 34; idx += 256) {
            int r = idx / 34, cc = idx - r * 34;
            int gy = 2 * tileY + r - 1;
            int gx = 2 * tileX + cc - 1;
            float v = 0.f;
            if (gy >= 0 && gy < Hin && gx >= 0 && gx < Win)
                v = ich[gy * Win + gx];
            s[r][cc] = v;
        }
        __syncthreads();

        const float* wp = w + (long long)(co * CIN + ci) * 9;
        #pragma unroll
        for (int ky = 0; ky < 3; ky++) {
            #pragma unroll
            for (int kx = 0; kx < 3; kx++) {
                float wv = wp[ky * 3 + kx];
                kadd(s00, c00, __fmul_rn(wv, s[ly + ky    ][lx + kx    ]));
                kadd(s01, c01, __fmul_rn(wv, s[ly + ky    ][lx + kx + 1]));
                kadd(s10, c10, __fmul_rn(wv, s[ly + ky + 1][lx + kx    ]));
                kadd(s11, c11, __fmul_rn(wv, s[ly + ky + 1][lx + kx + 1]));
            }
        }
        __syncthreads();
    }

    float bv = bias[co];
    float a00 = fmaxf(__fadd_rn(s00, bv), 0.f);
    float a01 = fmaxf(__fadd_rn(s01, bv), 0.f);
    float a10 = fmaxf(__fadd_rn(s10, bv), 0.f);
    float a11 = fmaxf(__fadd_rn(s11, bv), 0.f);
    float m = fmaxf(fmaxf(a00, a01), fmaxf(a10, a11));

    const int py = tileY + ty, px = tileX + tx;
    out[(((long long)b * CO + co) * Hp + py) * Wp + px] = m;
}

// ---------------------------------------------------------------------------
// 1x1 head conv (Kahan fp32): x4 [8,256,32,32] * wh[5,256] + bh -> pred
// ---------------------------------------------------------------------------
__global__ void head_kernel(const float* __restrict__ wh,
                            const float* __restrict__ bh) {
    __shared__ float ws[5 * 256];
    int tid = threadIdx.x;
    for (int i = tid; i < 5 * 256; i += blockDim.x) ws[i] = wh[i];
    __syncthreads();

    int cell = blockIdx.x * blockDim.x + tid;
    if (cell >= BB * NCELL) return;
    int b = cell >> 10;
    int s = cell & (NCELL - 1);

    float a0 = 0.f, k0 = 0.f, a1 = 0.f, k1 = 0.f, a2 = 0.f, k2 = 0.f;
    float a3 = 0.f, k3 = 0.f, a4 = 0.f, k4 = 0.f;
    const float* xb = g_x4 + ((long long)b * 256) * NCELL + s;
    for (int ci = 0; ci < 256; ci++) {
        float v = xb[ci * NCELL];
        kadd(a0, k0, __fmul_rn(ws[0 * 256 + ci], v));
        kadd(a1, k1, __fmul_rn(ws[1 * 256 + ci], v));
        kadd(a2, k2, __fmul_rn(ws[2 * 256 + ci], v));
        kadd(a3, k3, __fmul_rn(ws[3 * 256 + ci], v));
        kadd(a4, k4, __fmul_rn(ws[4 * 256 + ci], v));
    }
    float* pb = g_pred + ((long long)b * 5) * NCELL + s;
    pb[0 * NCELL] = __fadd_rn(a0, bh[0]);
    pb[1 * NCELL] = __fadd_rn(a1, bh[1]);
    pb[2 * NCELL] = __fadd_rn(a2, bh[2]);
    pb[3 * NCELL] = __fadd_rn(a3, bh[3]);
    pb[4 * NCELL] = __fadd_rn(a4, bh[4]);
}

// ---------------------------------------------------------------------------
// Decode + top-200 (bitonic full sort: score desc, index asc — matches
// lax.top_k tie-break) + greedy NMS. One CTA of 1024 threads per batch.
// Transcendentals in double then rounded (correctly-rounded fp32 values);
// elementwise arithmetic via __f*_rn mirroring jnp op-by-op.
// ---------------------------------------------------------------------------
__device__ __forceinline__ float sigmoid_d(float x) {
    return (float)(1.0 / (1.0 + exp(-(double)x)));
}

__global__ void decode_nms_kernel(float* __restrict__ out, int out_size) {
    const int b = blockIdx.x;
    const int t = threadIdx.x;

    __shared__ float sc[NCELL];
    __shared__ int   si[NCELL];
    __shared__ float bx1[TOPK], by1[TOPK], bx2[TOPK], by2[TOPK];
    __shared__ float bar[TOPK], bsv[TOPK];
    __shared__ int   keepS[TOPK];

    const float* pb = g_pred + (long long)b * 5 * NCELL;

    {
        float obj = sigmoid_d(pb[t]);
        sc[t] = (obj >= SCORE_T) ? obj : -1.0f;
        si[t] = t;
    }
    __syncthreads();

    for (int k = 2; k <= NCELL; k <<= 1) {
        for (int j = k >> 1; j > 0; j >>= 1) {
            int ixj = t ^ j;
            if (ixj > t) {
                float a = sc[t], c = sc[ixj];
                int   ia = si[t], ic = si[ixj];
                bool aAfter = (a < c) || (a == c && ia > ic);
                bool descRegion = ((t & k) == 0);
                if (descRegion ? aAfter : !aAfter) {
                    sc[t] = c;  sc[ixj] = a;
                    si[t] = ic; si[ixj] = ia;
                }
            }
            __syncthreads();
        }
    }

    if (t < TOPK) {
        int cell = si[t];
        float sval = sc[t];
        float p1 = pb[1 * NCELL + cell];
        float p2 = pb[2 * NCELL + cell];
        float p3 = pb[3 * NCELL + cell];
        float p4 = pb[4 * NCELL + cell];
        const float sx = 16.0f;   // W / Gw
        const float sy = 16.0f;   // H / Gh
        float txv = sigmoid_d(p1);
        float tyv = sigmoid_d(p2);
        float bw  = __fmul_rn((float)exp((double)p3), sx);
        float bh_ = __fmul_rn((float)exp((double)p4), sy);
        float gx = (float)(cell & (GRID - 1));
        float gy = (float)(cell >> 5);
        float cx = __fadd_rn(__fmul_rn(gx, sx), __fmul_rn(txv, sx));
        float cy = __fadd_rn(__fmul_rn(gy, sy), __fmul_rn(tyv, sy));
        float hw = __fmul_rn(bw, 0.5f);   // exact
        float hh = __fmul_rn(bh_, 0.5f);  // exact
        float x1 = fminf(fmaxf(__fsub_rn(cx, hw), 0.f), 511.0f);
        float y1 = fminf(fmaxf(__fsub_rn(cy, hh), 0.f), 511.0f);
        float x2 = fminf(fmaxf(__fadd_rn(cx, hw), 0.f), 511.0f);
        float y2 = fminf(fmaxf(__fadd_rn(cy, hh), 0.f), 511.0f);
        bx1[t] = x1; by1[t] = y1; bx2[t] = x2; by2[t] = y2;
        bar[t] = __fmul_rn(__fsub_rn(x2, x1), __fsub_rn(y2, y1));
        bsv[t] = sval;
        keepS[t] = (sval >= SCORE_T) ? 1 : 0;
    }

    for (int i = 0; i < TOPK; i++) {
        __syncthreads();
        if (keepS[i] && t > i && t < TOPK && keepS[t]) {
            float xx1 = fmaxf(bx1[i], bx1[t]);
            float yy1 = fmaxf(by1[i], by1[t]);
            float xx2 = fminf(bx2[i], bx2[t]);
            float yy2 = fminf(by2[i], by2[t]);
            float iw = fmaxf(__fsub_rn(xx2, xx1), 0.f);
            float ih = fmaxf(__fsub_rn(yy2, yy1), 0.f);
            float inter = __fmul_rn(iw, ih);
            float uni = __fsub_rn(__fadd_rn(bar[i], bar[t]), inter);
            float iou = __fdiv_rn(inter, fmaxf(uni, 1e-6f));
            if (iou > IOU_T) keepS[t] = 0;
        }
    }
    __syncthreads();

    if (t < TOPK) {
        float kf = keepS[t] ? 1.0f : 0.0f;
        float* o = out + ((long long)(b * TOPK + t)) * 5;
        o[0] = __fmul_rn(bx1[t], kf);
        o[1] = __fmul_rn(by1[t], kf);
        o[2] = __fmul_rn(bx2[t], kf);
        o[3] = __fmul_rn(by2[t], kf);
        o[4] = __fmul_rn(bsv[t], kf);
        if (out_size >= BB * TOPK * 5 + BB * TOPK) {
            out[BB * TOPK * 5 + b * TOPK + t] = kf;
        }
    }
}

// ---------------------------------------------------------------------------
// Host launch
// ---------------------------------------------------------------------------
extern "C" void kernel_launch(void* const* d_in, const int* in_sizes, int n_in,
                              void* d_out, int out_size) {
    const float* images = (const float*)d_in[0];
    const float* w1 = (const float*)d_in[1];
    const float* b1 = (const float*)d_in[2];
    const float* w2 = (const float*)d_in[3];
    const float* b2 = (const float*)d_in[4];
    const float* w3 = (const float*)d_in[5];
    const float* b3 = (const float*)d_in[6];
    const float* w4 = (const float*)d_in[7];
    const float* b4 = (const float*)d_in[8];
    const float* wh = (const float*)d_in[9];
    const float* bh = (const float*)d_in[10];

    float *x1p, *x2p, *x3p, *x4p;
    cudaGetSymbolAddress((void**)&x1p, g_x1);
    cudaGetSymbolAddress((void**)&x2p, g_x2);
    cudaGetSymbolAddress((void**)&x3p, g_x3);
    cudaGetSymbolAddress((void**)&x4p, g_x4);

    dim3 blk(16, 16);
    conv_relu_pool_kernel<<<dim3(16, 16, BB * 32), blk>>>(
        images, w1, b1, x1p, 3, 32, 512, 512);
    conv_relu_pool_kernel<<<dim3(8, 8, BB * 64), blk>>>(
        x1p, w2, b2, x2p, 32, 64, 256, 256);
    conv_relu_pool_kernel<<<dim3(4, 4, BB * 128), blk>>>(
        x2p, w3, b3, x3p, 64, 128, 128, 128);
    conv_relu_pool_kernel<<<dim3(2, 2, BB * 256), blk>>>(
        x3p, w4, b4, x4p, 128, 256, 64, 64);
    head_kernel<<<(BB * NCELL + 255) / 256, 256>>>(wh, bh);
    decode_nms_kernel<<<BB, NCELL>>>((float*)d_out, out_size);
}

// round 8
// speedup vs baseline: 2.7985x; 2.7985x over previous
#include <cuda_runtime.h>
#include <cuda_bf16.h>
#include <math.h>

// ---------------------------------------------------------------------------
// Problem constants
// ---------------------------------------------------------------------------
#define BB 8
#define HH 512
#define WW 512
#define TOPK 200
#define SCORE_T 0.01f
#define IOU_T 0.5f
#define GRID 32           // Gh = Gw = 32
#define NCELL (GRID*GRID) // 1024

// ---------------------------------------------------------------------------
// Scratch (static device arrays; no allocation allowed)
// ---------------------------------------------------------------------------
__device__ float g_x1[BB * 32  * 256 * 256];   // 64 MB
__device__ float g_x2[BB * 64  * 128 * 128];   // 32 MB
__device__ float g_x3[BB * 128 * 64  * 64 ];   // 16 MB
__device__ float g_x4[BB * 256 * 32  * 32 ];   //  8 MB
__device__ float g_pred[BB * 5 * NCELL];

// Kahan compensated add. __f*_rn intrinsics block reassociation/contraction.
__device__ __forceinline__ void kadd(float& s, float& c, float term) {
    float y = __fsub_rn(term, c);
    float t = __fadd_rn(s, y);
    c = __fsub_rn(__fsub_rn(t, s), y);
    s = t;
}

// ---------------------------------------------------------------------------
// Fused conv3x3(SAME) + bias + ReLU + maxpool2x2.
// NCO output channels per block; 256 threads -> 16x16 pooled tile.
// Each thread: 4x4 input window in registers -> 2x2 conv outputs -> 1 pooled
// pixel, for each of NCO output channels.
// Accuracy scheme: plain FMA partial over groups of 8 input channels,
// Kahan-folded into the running sum (end-to-end ~1e-7 rel, vs 1e-3 threshold).
// ---------------------------------------------------------------------------
template<int CIN, int NCO>
__global__ void __launch_bounds__(256, 2)
conv_relu_pool_t(const float* __restrict__ in,
                 const float* __restrict__ w,
                 const float* __restrict__ bias,
                 float* __restrict__ out,
                 int CO, int Hin, int Win) {
    const int Hp = Hin >> 1, Wp = Win >> 1;
    const int tid = threadIdx.x;
    const int tx = tid & 15, ty = tid >> 4;
    const int tileX = blockIdx.x * 16, tileY = blockIdx.y * 16;
    const int z   = blockIdx.z;
    const int nCog = CO / NCO;
    const int cog = z % nCog;
    const int b   = z / nCog;
    const int co0 = cog * NCO;

    __shared__ float s[34][36];

    float sum[NCO * 4], comp[NCO * 4], part[NCO * 4];
    #pragma unroll
    for (int i = 0; i < NCO * 4; i++) { sum[i] = 0.f; comp[i] = 0.f; part[i] = 0.f; }

    const int lx = 2 * tx;
    const int ly = 2 * ty;
    const float* inb = in + (long long)b * CIN * Hin * Win;

    for (int ci = 0; ci < CIN; ci++) {
        if (ci) __syncthreads();
        const float* ich = inb + (long long)ci * Hin * Win;
        #pragma unroll
        for (int k = 0; k < 5; k++) {
            int idx = tid + k * 256;
            if (idx < 34 * 34) {
                int r = idx / 34, cc = idx - r * 34;
                int gy = 2 * tileY + r - 1;
                int gx = 2 * tileX + cc - 1;
                float v = 0.f;
                if (gy >= 0 && gy < Hin && gx >= 0 && gx < Win)
                    v = ich[gy * Win + gx];
                s[r][cc] = v;
            }
        }
        __syncthreads();

        // hoist 4x4 input window into registers
        float d[16];
        #pragma unroll
        for (int r = 0; r < 4; r++)
            #pragma unroll
            for (int c = 0; c < 4; c++)
                d[r * 4 + c] = s[ly + r][lx + c];

        #pragma unroll
        for (int co = 0; co < NCO; co++) {
            const float* wp = w + (long long)((co0 + co) * CIN + ci) * 9;
            float wr[9];
            #pragma unroll
            for (int k = 0; k < 9; k++) wr[k] = __ldg(wp + k);
            #pragma unroll
            for (int ky = 0; ky < 3; ky++) {
                #pragma unroll
                for (int kx = 0; kx < 3; kx++) {
                    float wv = wr[ky * 3 + kx];
                    part[co * 4 + 0] = fmaf(wv, d[(ky    ) * 4 + kx    ], part[co * 4 + 0]);
                    part[co * 4 + 1] = fmaf(wv, d[(ky    ) * 4 + kx + 1], part[co * 4 + 1]);
                    part[co * 4 + 2] = fmaf(wv, d[(ky + 1) * 4 + kx    ], part[co * 4 + 2]);
                    part[co * 4 + 3] = fmaf(wv, d[(ky + 1) * 4 + kx + 1], part[co * 4 + 3]);
                }
            }
        }

        if ((ci & 7) == 7 || ci == CIN - 1) {
            #pragma unroll
            for (int i = 0; i < NCO * 4; i++) {
                kadd(sum[i], comp[i], part[i]);
                part[i] = 0.f;
            }
        }
    }

    const int py = tileY + ty, px = tileX + tx;
    #pragma unroll
    for (int co = 0; co < NCO; co++) {
        float bv = bias[co0 + co];
        float a00 = fmaxf(__fadd_rn(sum[co * 4 + 0], bv), 0.f);
        float a01 = fmaxf(__fadd_rn(sum[co * 4 + 1], bv), 0.f);
        float a10 = fmaxf(__fadd_rn(sum[co * 4 + 2], bv), 0.f);
        float a11 = fmaxf(__fadd_rn(sum[co * 4 + 3], bv), 0.f);
        float m = fmaxf(fmaxf(a00, a01), fmaxf(a10, a11));
        out[(((long long)b * CO + co0 + co) * Hp + py) * Wp + px] = m;
    }
}

// ---------------------------------------------------------------------------
// 1x1 head conv (Kahan fp32): x4 [8,256,32,32] * wh[5,256] + bh -> pred
// ---------------------------------------------------------------------------
__global__ void head_kernel(const float* __restrict__ wh,
                            const float* __restrict__ bh) {
    __shared__ float ws[5 * 256];
    int tid = threadIdx.x;
    for (int i = tid; i < 5 * 256; i += blockDim.x) ws[i] = wh[i];
    __syncthreads();

    int cell = blockIdx.x * blockDim.x + tid;
    if (cell >= BB * NCELL) return;
    int b = cell >> 10;
    int s = cell & (NCELL - 1);

    float a0 = 0.f, k0 = 0.f, a1 = 0.f, k1 = 0.f, a2 = 0.f, k2 = 0.f;
    float a3 = 0.f, k3 = 0.f, a4 = 0.f, k4 = 0.f;
    const float* xb = g_x4 + ((long long)b * 256) * NCELL + s;
    for (int ci = 0; ci < 256; ci++) {
        float v = xb[ci * NCELL];
        kadd(a0, k0, __fmul_rn(ws[0 * 256 + ci], v));
        kadd(a1, k1, __fmul_rn(ws[1 * 256 + ci], v));
        kadd(a2, k2, __fmul_rn(ws[2 * 256 + ci], v));
        kadd(a3, k3, __fmul_rn(ws[3 * 256 + ci], v));
        kadd(a4, k4, __fmul_rn(ws[4 * 256 + ci], v));
    }
    float* pb = g_pred + ((long long)b * 5) * NCELL + s;
    pb[0 * NCELL] = __fadd_rn(a0, bh[0]);
    pb[1 * NCELL] = __fadd_rn(a1, bh[1]);
    pb[2 * NCELL] = __fadd_rn(a2, bh[2]);
    pb[3 * NCELL] = __fadd_rn(a3, bh[3]);
    pb[4 * NCELL] = __fadd_rn(a4, bh[4]);
}

// ---------------------------------------------------------------------------
// Decode + top-200 (bitonic full sort: score desc, index asc — matches
// lax.top_k tie-break) + greedy NMS. One CTA of 1024 threads per batch.
// ---------------------------------------------------------------------------
__device__ __forceinline__ float sigmoid_d(float x) {
    return (float)(1.0 / (1.0 + exp(-(double)x)));
}

__global__ void decode_nms_kernel(float* __restrict__ out, int out_size) {
    const int b = blockIdx.x;
    const int t = threadIdx.x;

    __shared__ float sc[NCELL];
    __shared__ int   si[NCELL];
    __shared__ float bx1[TOPK], by1[TOPK], bx2[TOPK], by2[TOPK];
    __shared__ float bar[TOPK], bsv[TOPK];
    __shared__ int   keepS[TOPK];

    const float* pb = g_pred + (long long)b * 5 * NCELL;

    {
        float obj = sigmoid_d(pb[t]);
        sc[t] = (obj >= SCORE_T) ? obj : -1.0f;
        si[t] = t;
    }
    __syncthreads();

    for (int k = 2; k <= NCELL; k <<= 1) {
        for (int j = k >> 1; j > 0; j >>= 1) {
            int ixj = t ^ j;
            if (ixj > t) {
                float a = sc[t], c = sc[ixj];
                int   ia = si[t], ic = si[ixj];
                bool aAfter = (a < c) || (a == c && ia > ic);
                bool descRegion = ((t & k) == 0);
                if (descRegion ? aAfter : !aAfter) {
                    sc[t] = c;  sc[ixj] = a;
                    si[t] = ic; si[ixj] = ia;
                }
            }
            __syncthreads();
        }
    }

    if (t < TOPK) {
        int cell = si[t];
        float sval = sc[t];
        float p1 = pb[1 * NCELL + cell];
        float p2 = pb[2 * NCELL + cell];
        float p3 = pb[3 * NCELL + cell];
        float p4 = pb[4 * NCELL + cell];
        const float sx = 16.0f;
        const float sy = 16.0f;
        float txv = sigmoid_d(p1);
        float tyv = sigmoid_d(p2);
        float bw  = __fmul_rn((float)exp((double)p3), sx);
        float bh_ = __fmul_rn((float)exp((double)p4), sy);
        float gx = (float)(cell & (GRID - 1));
        float gy = (float)(cell >> 5);
        float cx = __fadd_rn(__fmul_rn(gx, sx), __fmul_rn(txv, sx));
        float cy = __fadd_rn(__fmul_rn(gy, sy), __fmul_rn(tyv, sy));
        float hw = __fmul_rn(bw, 0.5f);
        float hh = __fmul_rn(bh_, 0.5f);
        float x1 = fminf(fmaxf(__fsub_rn(cx, hw), 0.f), 511.0f);
        float y1 = fminf(fmaxf(__fsub_rn(cy, hh), 0.f), 511.0f);
        float x2 = fminf(fmaxf(__fadd_rn(cx, hw), 0.f), 511.0f);
        float y2 = fminf(fmaxf(__fadd_rn(cy, hh), 0.f), 511.0f);
        bx1[t] = x1; by1[t] = y1; bx2[t] = x2; by2[t] = y2;
        bar[t] = __fmul_rn(__fsub_rn(x2, x1), __fsub_rn(y2, y1));
        bsv[t] = sval;
        keepS[t] = (sval >= SCORE_T) ? 1 : 0;
    }

    for (int i = 0; i < TOPK; i++) {
        __syncthreads();
        if (keepS[i] && t > i && t < TOPK && keepS[t]) {
            float xx1 = fmaxf(bx1[i], bx1[t]);
            float yy1 = fmaxf(by1[i], by1[t]);
            float xx2 = fminf(bx2[i], bx2[t]);
            float yy2 = fminf(by2[i], by2[t]);
            float iw = fmaxf(__fsub_rn(xx2, xx1), 0.f);
            float ih = fmaxf(__fsub_rn(yy2, yy1), 0.f);
            float inter = __fmul_rn(iw, ih);
            float uni = __fsub_rn(__fadd_rn(bar[i], bar[t]), inter);
            float iou = __fdiv_rn(inter, fmaxf(uni, 1e-6f));
            if (iou > IOU_T) keepS[t] = 0;
        }
    }
    __syncthreads();

    if (t < TOPK) {
        float kf = keepS[t] ? 1.0f : 0.0f;
        float* o = out + ((long long)(b * TOPK + t)) * 5;
        o[0] = __fmul_rn(bx1[t], kf);
        o[1] = __fmul_rn(by1[t], kf);
        o[2] = __fmul_rn(bx2[t], kf);
        o[3] = __fmul_rn(by2[t], kf);
        o[4] = __fmul_rn(bsv[t], kf);
        if (out_size >= BB * TOPK * 5 + BB * TOPK) {
            out[BB * TOPK * 5 + b * TOPK + t] = kf;
        }
    }
}

// ---------------------------------------------------------------------------
// Host launch
// ---------------------------------------------------------------------------
extern "C" void kernel_launch(void* const* d_in, const int* in_sizes, int n_in,
                              void* d_out, int out_size) {
    const float* images = (const float*)d_in[0];
    const float* w1 = (const float*)d_in[1];
    const float* b1 = (const float*)d_in[2];
    const float* w2 = (const float*)d_in[3];
    const float* b2 = (const float*)d_in[4];
    const float* w3 = (const float*)d_in[5];
    const float* b3 = (const float*)d_in[6];
    const float* w4 = (const float*)d_in[7];
    const float* b4 = (const float*)d_in[8];
    const float* wh = (const float*)d_in[9];
    const float* bh = (const float*)d_in[10];

    float *x1p, *x2p, *x3p, *x4p;
    cudaGetSymbolAddress((void**)&x1p, g_x1);
    cudaGetSymbolAddress((void**)&x2p, g_x2);
    cudaGetSymbolAddress((void**)&x3p, g_x3);
    cudaGetSymbolAddress((void**)&x4p, g_x4);

    // L1: [8,3,512,512] -> [8,32,256,256]
    conv_relu_pool_t<3, 4><<<dim3(16, 16, BB * (32 / 4)), 256>>>(
        images, w1, b1, x1p, 32, 512, 512);
    // L2: -> [8,64,128,128]
    conv_relu_pool_t<32, 4><<<dim3(8, 8, BB * (64 / 4)), 256>>>(
        x1p, w2, b2, x2p, 64, 256, 256);
    // L3: -> [8,128,64,64]
    conv_relu_pool_t<64, 4><<<dim3(4, 4, BB * (128 / 4)), 256>>>(
        x2p, w3, b3, x3p, 128, 128, 128);
    // L4: -> [8,256,32,32]
    conv_relu_pool_t<128, 4><<<dim3(2, 2, BB * (256 / 4)), 256>>>(
        x3p, w4, b4, x4p, 256, 64, 64);
    // head 1x1
    head_kernel<<<(BB * NCELL + 255) / 256, 256>>>(wh, bh);
    // decode + topk + nms
    decode_nms_kernel<<<BB, NCELL>>>((float*)d_out, out_size);
}

// round 13
// speedup vs baseline: 3.9945x; 1.4274x over previous
#include <cuda_runtime.h>
#include <cuda_bf16.h>
#include <cstdint>
#include <math.h>

// ---------------------------------------------------------------------------
// Problem constants
// ---------------------------------------------------------------------------
#define BB 8
#define HH 512
#define WW 512
#define TOPK 200
#define SCORE_T 0.01f
#define IOU_T 0.5f
#define GRID 32           // Gh = Gw = 32
#define NCELL (GRID*GRID) // 1024

// ---------------------------------------------------------------------------
// Scratch (static device arrays; no allocation allowed)
// ---------------------------------------------------------------------------
__device__ float g_x1[BB * 32  * 256 * 256];   // 64 MB
__device__ float g_x2[BB * 64  * 128 * 128];   // 32 MB
__device__ float g_x3[BB * 128 * 64  * 64 ];   // 16 MB
__device__ float g_x4[BB * 256 * 32  * 32 ];   //  8 MB
__device__ float g_pred[BB * 5 * NCELL];

// Kahan compensated add. __f*_rn intrinsics block reassociation/contraction.
__device__ __forceinline__ void kadd(float& s, float& c, float term) {
    float y = __fsub_rn(term, c);
    float t = __fadd_rn(s, y);
    c = __fsub_rn(__fsub_rn(t, s), y);
    s = t;
}

__device__ __forceinline__ void cp_async4(unsigned int saddr, const void* gaddr, int src_sz) {
    asm volatile("cp.async.ca.shared.global [%0], [%1], 4, %2;"
                 :: "r"(saddr), "l"(gaddr), "r"(src_sz) : "memory");
}
__device__ __forceinline__ void cp_commit() {
    asm volatile("cp.async.commit_group;" ::: "memory");
}

// ---------------------------------------------------------------------------
// Fused conv3x3(SAME) + bias + ReLU + maxpool2x2.
// NCO output channels per block; 256 threads -> 16x16 pooled tile.
// G input channels are staged per barrier phase via double-buffered cp.async,
// overlapping gmem->smem transfer of group g+1 with FMA work of group g.
// Numerics: plain-FMA partials folded into a Kahan-compensated sum every
// 8 input channels (identical grouping to the previous passing version).
// ---------------------------------------------------------------------------
template<int CIN, int NCO, int G>
__global__ void __launch_bounds__(256, 2)
conv_relu_pool_t(const float* __restrict__ in,
                 const float* __restrict__ w,
                 const float* __restrict__ bias,
                 float* __restrict__ out,
                 int CO, int Hin, int Win) {
    constexpr int NG = CIN / G;               // groups per block (CIN % G == 0)
    constexpr int ELEMS = G * 34 * 34;        // smem elements per group
    constexpr int LOADS = (ELEMS + 255) / 256;

    const int Hp = Hin >> 1, Wp = Win >> 1;
    const int tid = threadIdx.x;
    const int tx = tid & 15, ty = tid >> 4;
    const int tileX = blockIdx.x * 16, tileY = blockIdx.y * 16;
    const int z   = blockIdx.z;
    const int nCog = CO / NCO;
    const int cog = z % nCog;
    const int b   = z / nCog;
    const int co0 = cog * NCO;

    __shared__ float tiles[2][G][34][36];
    const unsigned int smem0 = (unsigned int)__cvta_generic_to_shared(&tiles[0][0][0][0]);

    const float* inb = in + (long long)b * CIN * Hin * Win;
    const long long chStride = (long long)Hin * Win;

    // issue async loads for input-channel group gg into buffer buf
    auto load_group = [&](int gg, int buf) {
        const float* base = inb + (long long)(gg * G) * chStride;
        #pragma unroll
        for (int k = 0; k < LOADS; k++) {
            int idx = tid + k * 256;
            if (idx < ELEMS) {
                int g   = idx / 1156;
                int rem = idx - g * 1156;
                int r   = rem / 34;
                int c   = rem - r * 34;
                int gy = 2 * tileY + r - 1;
                int gx = 2 * tileX + c - 1;
                bool ok = (gy >= 0) && (gy < Hin) && (gx >= 0) && (gx < Win);
                const float* src = ok ? (base + g * chStride + (long long)gy * Win + gx)
                                      : base;
                unsigned int dst = smem0 + (unsigned int)((((buf * G + g) * 34 + r) * 36 + c) * 4);
                cp_async4(dst, src, ok ? 4 : 0);
            }
        }
        cp_commit();
    };

    float sum[NCO * 4], comp[NCO * 4], part[NCO * 4];
    #pragma unroll
    for (int i = 0; i < NCO * 4; i++) { sum[i] = 0.f; comp[i] = 0.f; part[i] = 0.f; }

    const int lx = 2 * tx;
    const int ly = 2 * ty;

    load_group(0, 0);

    for (int gg = 0; gg < NG; gg++) {
        const int buf = gg & 1;
        if (gg + 1 < NG) {
            load_group(gg + 1, buf ^ 1);
            asm volatile("cp.async.wait_group %0;" :: "n"(1) : "memory");
        } else {
            asm volatile("cp.async.wait_group %0;" :: "n"(0) : "memory");
        }
        __syncthreads();

        #pragma unroll
        for (int g = 0; g < G; g++) {
            // hoist 4x4 input window into registers
            float d[16];
            #pragma unroll
            for (int r = 0; r < 4; r++)
                #pragma unroll
                for (int c = 0; c < 4; c++)
                    d[r * 4 + c] = tiles[buf][g][ly + r][lx + c];

            const int ci = gg * G + g;
            #pragma unroll
            for (int co = 0; co < NCO; co++) {
                const float* wp = w + (long long)((co0 + co) * CIN + ci) * 9;
                float wr[9];
                #pragma unroll
                for (int k = 0; k < 9; k++) wr[k] = __ldg(wp + k);
                #pragma unroll
                for (int ky = 0; ky < 3; ky++) {
                    #pragma unroll
                    for (int kx = 0; kx < 3; kx++) {
                        float wv = wr[ky * 3 + kx];
                        part[co * 4 + 0] = fmaf(wv, d[(ky    ) * 4 + kx    ], part[co * 4 + 0]);
                        part[co * 4 + 1] = fmaf(wv, d[(ky    ) * 4 + kx + 1], part[co * 4 + 1]);
                        part[co * 4 + 2] = fmaf(wv, d[(ky + 1) * 4 + kx    ], part[co * 4 + 2]);
                        part[co * 4 + 3] = fmaf(wv, d[(ky + 1) * 4 + kx + 1], part[co * 4 + 3]);
                    }
                }
            }
        }

        // fold every 8 input channels (2 groups of 4), same as previous version
        if ((gg & 1) || gg == NG - 1) {
            #pragma unroll
            for (int i = 0; i < NCO * 4; i++) {
                kadd(sum[i], comp[i], part[i]);
                part[i] = 0.f;
            }
        }
        __syncthreads();   // protect buffer reuse (group gg+2 overwrites buf)
    }

    const int py = tileY + ty, px = tileX + tx;
    #pragma unroll
    for (int co = 0; co < NCO; co++) {
        float bv = bias[co0 + co];
        float a00 = fmaxf(__fadd_rn(sum[co * 4 + 0], bv), 0.f);
        float a01 = fmaxf(__fadd_rn(sum[co * 4 + 1], bv), 0.f);
        float a10 = fmaxf(__fadd_rn(sum[co * 4 + 2], bv), 0.f);
        float a11 = fmaxf(__fadd_rn(sum[co * 4 + 3], bv), 0.f);
        float m = fmaxf(fmaxf(a00, a01), fmaxf(a10, a11));
        out[(((long long)b * CO + co0 + co) * Hp + py) * Wp + px] = m;
    }
}

// ---------------------------------------------------------------------------
// 1x1 head conv (Kahan fp32): x4 [8,256,32,32] * wh[5,256] + bh -> pred
// ---------------------------------------------------------------------------
__global__ void head_kernel(const float* __restrict__ wh,
                            const float* __restrict__ bh) {
    __shared__ float ws[5 * 256];
    int tid = threadIdx.x;
    for (int i = tid; i < 5 * 256; i += blockDim.x) ws[i] = wh[i];
    __syncthreads();

    int cell = blockIdx.x * blockDim.x + tid;
    if (cell >= BB * NCELL) return;
    int b = cell >> 10;
    int s = cell & (NCELL - 1);

    float a0 = 0.f, k0 = 0.f, a1 = 0.f, k1 = 0.f, a2 = 0.f, k2 = 0.f;
    float a3 = 0.f, k3 = 0.f, a4 = 0.f, k4 = 0.f;
    const float* xb = g_x4 + ((long long)b * 256) * NCELL + s;
    for (int ci = 0; ci < 256; ci++) {
        float v = xb[ci * NCELL];
        kadd(a0, k0, __fmul_rn(ws[0 * 256 + ci], v));
        kadd(a1, k1, __fmul_rn(ws[1 * 256 + ci], v));
        kadd(a2, k2, __fmul_rn(ws[2 * 256 + ci], v));
        kadd(a3, k3, __fmul_rn(ws[3 * 256 + ci], v));
        kadd(a4, k4, __fmul_rn(ws[4 * 256 + ci], v));
    }
    float* pb = g_pred + ((long long)b * 5) * NCELL + s;
    pb[0 * NCELL] = __fadd_rn(a0, bh[0]);
    pb[1 * NCELL] = __fadd_rn(a1, bh[1]);
    pb[2 * NCELL] = __fadd_rn(a2, bh[2]);
    pb[3 * NCELL] = __fadd_rn(a3, bh[3]);
    pb[4 * NCELL] = __fadd_rn(a4, bh[4]);
}

// ---------------------------------------------------------------------------
// Decode + top-200 (bitonic full sort: score desc, index asc — matches
// lax.top_k tie-break) + greedy NMS. One CTA of 1024 threads per batch.
// ---------------------------------------------------------------------------
__device__ __forceinline__ float sigmoid_d(float x) {
    return (float)(1.0 / (1.0 + exp(-(double)x)));
}

__global__ void decode_nms_kernel(float* __restrict__ out, int out_size) {
    const int b = blockIdx.x;
    const int t = threadIdx.x;

    __shared__ float sc[NCELL];
    __shared__ int   si[NCELL];
    __shared__ float bx1[TOPK], by1[TOPK], bx2[TOPK], by2[TOPK];
    __shared__ float bar[TOPK], bsv[TOPK];
    __shared__ int   keepS[TOPK];

    const float* pb = g_pred + (long long)b * 5 * NCELL;

    {
        float obj = sigmoid_d(pb[t]);
        sc[t] = (obj >= SCORE_T) ? obj : -1.0f;
        si[t] = t;
    }
    __syncthreads();

    for (int k = 2; k <= NCELL; k <<= 1) {
        for (int j = k >> 1; j > 0; j >>= 1) {
            int ixj = t ^ j;
            if (ixj > t) {
                float a = sc[t], c = sc[ixj];
                int   ia = si[t], ic = si[ixj];
                bool aAfter = (a < c) || (a == c && ia > ic);
                bool descRegion = ((t & k) == 0);
                if (descRegion ? aAfter : !aAfter) {
                    sc[t] = c;  sc[ixj] = a;
                    si[t] = ic; si[ixj] = ia;
                }
            }
            __syncthreads();
        }
    }

    if (t < TOPK) {
        int cell = si[t];
        float sval = sc[t];
        float p1 = pb[1 * NCELL + cell];
        float p2 = pb[2 * NCELL + cell];
        float p3 = pb[3 * NCELL + cell];
        float p4 = pb[4 * NCELL + cell];
        const float sx = 16.0f;
        const float sy = 16.0f;
        float txv = sigmoid_d(p1);
        float tyv = sigmoid_d(p2);
        float bw  = __fmul_rn((float)exp((double)p3), sx);
        float bh_ = __fmul_rn((float)exp((double)p4), sy);
        float gx = (float)(cell & (GRID - 1));
        float gy = (float)(cell >> 5);
        float cx = __fadd_rn(__fmul_rn(gx, sx), __fmul_rn(txv, sx));
        float cy = __fadd_rn(__fmul_rn(gy, sy), __fmul_rn(tyv, sy));
        float hw = __fmul_rn(bw, 0.5f);
        float hh = __fmul_rn(bh_, 0.5f);
        float x1 = fminf(fmaxf(__fsub_rn(cx, hw), 0.f), 511.0f);
        float y1 = fminf(fmaxf(__fsub_rn(cy, hh), 0.f), 511.0f);
        float x2 = fminf(fmaxf(__fadd_rn(cx, hw), 0.f), 511.0f);
        float y2 = fminf(fmaxf(__fadd_rn(cy, hh), 0.f), 511.0f);
        bx1[t] = x1; by1[t] = y1; bx2[t] = x2; by2[t] = y2;
        bar[t] = __fmul_rn(__fsub_rn(x2, x1), __fsub_rn(y2, y1));
        bsv[t] = sval;
        keepS[t] = (sval >= SCORE_T) ? 1 : 0;
    }

    for (int i = 0; i < TOPK; i++) {
        __syncthreads();
        if (keepS[i] && t > i && t < TOPK && keepS[t]) {
            float xx1 = fmaxf(bx1[i], bx1[t]);
            float yy1 = fmaxf(by1[i], by1[t]);
            float xx2 = fminf(bx2[i], bx2[t]);
            float yy2 = fminf(by2[i], by2[t]);
            float iw = fmaxf(__fsub_rn(xx2, xx1), 0.f);
            float ih = fmaxf(__fsub_rn(yy2, yy1), 0.f);
            float inter = __fmul_rn(iw, ih);
            float uni = __fsub_rn(__fadd_rn(bar[i], bar[t]), inter);
            float iou = __fdiv_rn(inter, fmaxf(uni, 1e-6f));
            if (iou > IOU_T) keepS[t] = 0;
        }
    }
    __syncthreads();

    if (t < TOPK) {
        float kf = keepS[t] ? 1.0f : 0.0f;
        float* o = out + ((long long)(b * TOPK + t)) * 5;
        o[0] = __fmul_rn(bx1[t], kf);
        o[1] = __fmul_rn(by1[t], kf);
        o[2] = __fmul_rn(bx2[t], kf);
        o[3] = __fmul_rn(by2[t], kf);
        o[4] = __fmul_rn(bsv[t], kf);
        if (out_size >= BB * TOPK * 5 + BB * TOPK) {
            out[BB * TOPK * 5 + b * TOPK + t] = kf;
        }
    }
}

// ---------------------------------------------------------------------------
// Host launch
// ---------------------------------------------------------------------------
extern "C" void kernel_launch(void* const* d_in, const int* in_sizes, int n_in,
                              void* d_out, int out_size) {
    const float* images = (const float*)d_in[0];
    const float* w1 = (const float*)d_in[1];
    const float* b1 = (const float*)d_in[2];
    const float* w2 = (const float*)d_in[3];
    const float* b2 = (const float*)d_in[4];
    const float* w3 = (const float*)d_in[5];
    const float* b3 = (const float*)d_in[6];
    const float* w4 = (const float*)d_in[7];
    const float* b4 = (const float*)d_in[8];
    const float* wh = (const float*)d_in[9];
    const float* bh = (const float*)d_in[10];

    float *x1p, *x2p, *x3p, *x4p;
    cudaGetSymbolAddress((void**)&x1p, g_x1);
    cudaGetSymbolAddress((void**)&x2p, g_x2);
    cudaGetSymbolAddress((void**)&x3p, g_x3);
    cudaGetSymbolAddress((void**)&x4p, g_x4);

    // L1: [8,3,512,512] -> [8,32,256,256]
    conv_relu_pool_t<3, 4, 3><<<dim3(16, 16, BB * (32 / 4)), 256>>>(
        images, w1, b1, x1p, 32, 512, 512);
    // L2: -> [8,64,128,128]
    conv_relu_pool_t<32, 4, 4><<<dim3(8, 8, BB * (64 / 4)), 256>>>(
        x1p, w2, b2, x2p, 64, 256, 256);
    // L3: -> [8,128,64,64]
    conv_relu_pool_t<64, 4, 4><<<dim3(4, 4, BB * (128 / 4)), 256>>>(
        x2p, w3, b3, x3p, 128, 128, 128);
    // L4: -> [8,256,32,32]
    conv_relu_pool_t<128, 4, 4><<<dim3(2, 2, BB * (256 / 4)), 256>>>(
        x3p, w4, b4, x4p, 256, 64, 64);
    // head 1x1
    head_kernel<<<(BB * NCELL + 255) / 256, 256>>>(wh, bh);
    // decode + topk + nms
    decode_nms_kernel<<<BB, NCELL>>>((float*)d_out, out_size);
}

// round 17
// speedup vs baseline: 4.8280x; 1.2086x over previous
#include <cuda_runtime.h>
#include <cuda_bf16.h>
#include <cstdint>
#include <math.h>

// ---------------------------------------------------------------------------
// Problem constants
// ---------------------------------------------------------------------------
#define BB 8
#define HH 512
#define WW 512
#define TOPK 200
#define SCORE_T 0.01f
#define IOU_T 0.5f
#define GRID 32           // Gh = Gw = 32
#define NCELL (GRID*GRID) // 1024

// ---------------------------------------------------------------------------
// Scratch (static device arrays; no allocation allowed)
// ---------------------------------------------------------------------------
__device__ float g_x1[BB * 32  * 256 * 256];   // 64 MB
__device__ float g_x2[BB * 64  * 128 * 128];   // 32 MB
__device__ float g_x3[BB * 128 * 64  * 64 ];   // 16 MB
__device__ float g_x4[BB * 256 * 32  * 32 ];   //  8 MB
__device__ float g_pred[BB * 5 * NCELL];

// Kahan compensated add. __f*_rn intrinsics block reassociation/contraction.
__device__ __forceinline__ void kadd(float& s, float& c, float term) {
    float y = __fsub_rn(term, c);
    float t = __fadd_rn(s, y);
    c = __fsub_rn(__fsub_rn(t, s), y);
    s = t;
}

__device__ __forceinline__ void cp_async4(unsigned int saddr, const void* gaddr, int src_sz) {
    asm volatile("cp.async.ca.shared.global [%0], [%1], 4, %2;"
                 :: "r"(saddr), "l"(gaddr), "r"(src_sz) : "memory");
}
__device__ __forceinline__ void cp_commit() {
    asm volatile("cp.async.commit_group;" ::: "memory");
}

// ---------------------------------------------------------------------------
// Fused conv3x3(SAME) + bias + ReLU + maxpool2x2.
// NCO output channels per block; 256 threads -> 16x16 pooled tile.
// G input channels per barrier phase, double-buffered cp.async staging.
// Weights staged ONCE per CTA into padded smem [ci][co][12] -> inner loop
// reads 2x LDS.128 + 1x LDS.32 (broadcast) instead of 9 LDG per (ci,co).
// Window reads vectorized as LDS.64 (lx even). FMA ordering identical to
// the previous passing version (Kahan fold every 8 input channels).
// ---------------------------------------------------------------------------
template<int CIN, int NCO, int G>
__global__ void __launch_bounds__(256, 2)
conv_relu_pool_t(const float* __restrict__ in,
                 const float* __restrict__ w,
                 const float* __restrict__ bias,
                 float* __restrict__ out,
                 int CO, int Hin, int Win) {
    constexpr int NG = CIN / G;               // groups per block (CIN % G == 0)
    constexpr int ELEMS = G * 34 * 34;        // smem elements per group
    constexpr int LOADS = (ELEMS + 255) / 256;

    const int Hp = Hin >> 1, Wp = Win >> 1;
    const int tid = threadIdx.x;
    const int tx = tid & 15, ty = tid >> 4;
    const int tileX = blockIdx.x * 16, tileY = blockIdx.y * 16;
    const int z   = blockIdx.z;
    const int nCog = CO / NCO;
    const int cog = z % nCog;
    const int b   = z / nCog;
    const int co0 = cog * NCO;

    __shared__ float tiles[2][G][34][36];
    __shared__ __align__(16) float wsm[CIN][NCO][12];
    const unsigned int smem0 = (unsigned int)__cvta_generic_to_shared(&tiles[0][0][0][0]);

    const float* inb = in + (long long)b * CIN * Hin * Win;
    const long long chStride = (long long)Hin * Win;

    // stage weights for this CTA's NCO output channels into smem
    for (int idx = tid; idx < CIN * NCO * 9; idx += 256) {
        int ci  = idx / (NCO * 9);
        int rem = idx - ci * (NCO * 9);
        int co  = rem / 9;
        int k   = rem - co * 9;
        wsm[ci][co][k] = w[((long long)(co0 + co) * CIN + ci) * 9 + k];
    }

    // issue async loads for input-channel group gg into buffer buf
    auto load_group = [&](int gg, int buf) {
        const float* base = inb + (long long)(gg * G) * chStride;
        #pragma unroll
        for (int k = 0; k < LOADS; k++) {
            int idx = tid + k * 256;
            if (idx < ELEMS) {
                int g   = idx / 1156;
                int rem = idx - g * 1156;
                int r   = rem / 34;
                int c   = rem - r * 34;
                int gy = 2 * tileY + r - 1;
                int gx = 2 * tileX + c - 1;
                bool ok = (gy >= 0) && (gy < Hin) && (gx >= 0) && (gx < Win);
                const float* src = ok ? (base + g * chStride + (long long)gy * Win + gx)
                                      : base;
                unsigned int dst = smem0 + (unsigned int)((((buf * G + g) * 34 + r) * 36 + c) * 4);
                cp_async4(dst, src, ok ? 4 : 0);
            }
        }
        cp_commit();
    };

    float sum[NCO * 4], comp[NCO * 4], part[NCO * 4];
    #pragma unroll
    for (int i = 0; i < NCO * 4; i++) { sum[i] = 0.f; comp[i] = 0.f; part[i] = 0.f; }

    const int lx = 2 * tx;
    const int ly = 2 * ty;

    load_group(0, 0);

    for (int gg = 0; gg < NG; gg++) {
        const int buf = gg & 1;
        if (gg + 1 < NG) {
            load_group(gg + 1, buf ^ 1);
            asm volatile("cp.async.wait_group %0;" :: "n"(1) : "memory");
        } else {
            asm volatile("cp.async.wait_group %0;" :: "n"(0) : "memory");
        }
        __syncthreads();   // tiles ready; also publishes wsm on first iteration

        #pragma unroll
        for (int g = 0; g < G; g++) {
            // 4x4 window via vectorized LDS.64 (lx is even -> 8B aligned)
            float d[16];
            #pragma unroll
            for (int r = 0; r < 4; r++) {
                float2 va = *(const float2*)&tiles[buf][g][ly + r][lx];
                float2 vb = *(const float2*)&tiles[buf][g][ly + r][lx + 2];
                d[r * 4 + 0] = va.x; d[r * 4 + 1] = va.y;
                d[r * 4 + 2] = vb.x; d[r * 4 + 3] = vb.y;
            }

            const int ci = gg * G + g;
            #pragma unroll
            for (int co = 0; co < NCO; co++) {
                const float4* wv4 = reinterpret_cast<const float4*>(&wsm[ci][co][0]);
                float4 wa = wv4[0];
                float4 wb = wv4[1];
                float  wc = wsm[ci][co][8];
                float wr[9] = {wa.x, wa.y, wa.z, wa.w, wb.x, wb.y, wb.z, wb.w, wc};
                #pragma unroll
                for (int ky = 0; ky < 3; ky++) {
                    #pragma unroll
                    for (int kx = 0; kx < 3; kx++) {
                        float wv = wr[ky * 3 + kx];
                        part[co * 4 + 0] = fmaf(wv, d[(ky    ) * 4 + kx    ], part[co * 4 + 0]);
                        part[co * 4 + 1] = fmaf(wv, d[(ky    ) * 4 + kx + 1], part[co * 4 + 1]);
                        part[co * 4 + 2] = fmaf(wv, d[(ky + 1) * 4 + kx    ], part[co * 4 + 2]);
                        part[co * 4 + 3] = fmaf(wv, d[(ky + 1) * 4 + kx + 1], part[co * 4 + 3]);
                    }
                }
            }
        }

        // fold every 8 input channels (2 groups of 4), same as previous version
        if ((gg & 1) || gg == NG - 1) {
            #pragma unroll
            for (int i = 0; i < NCO * 4; i++) {
                kadd(sum[i], comp[i], part[i]);
                part[i] = 0.f;
            }
        }
        __syncthreads();   // protect buffer reuse (group gg+2 overwrites buf)
    }

    const int py = tileY + ty, px = tileX + tx;
    #pragma unroll
    for (int co = 0; co < NCO; co++) {
        float bv = bias[co0 + co];
        float a00 = fmaxf(__fadd_rn(sum[co * 4 + 0], bv), 0.f);
        float a01 = fmaxf(__fadd_rn(sum[co * 4 + 1], bv), 0.f);
        float a10 = fmaxf(__fadd_rn(sum[co * 4 + 2], bv), 0.f);
        float a11 = fmaxf(__fadd_rn(sum[co * 4 + 3], bv), 0.f);
        float m = fmaxf(fmaxf(a00, a01), fmaxf(a10, a11));
        out[(((long long)b * CO + co0 + co) * Hp + py) * Wp + px] = m;
    }
}

// ---------------------------------------------------------------------------
// 1x1 head conv (Kahan fp32): x4 [8,256,32,32] * wh[5,256] + bh -> pred
// ---------------------------------------------------------------------------
__global__ void head_kernel(const float* __restrict__ wh,
                            const float* __restrict__ bh) {
    __shared__ float ws[5 * 256];
    int tid = threadIdx.x;
    for (int i = tid; i < 5 * 256; i += blockDim.x) ws[i] = wh[i];
    __syncthreads();

    int cell = blockIdx.x * blockDim.x + tid;
    if (cell >= BB * NCELL) return;
    int b = cell >> 10;
    int s = cell & (NCELL - 1);

    float a0 = 0.f, k0 = 0.f, a1 = 0.f, k1 = 0.f, a2 = 0.f, k2 = 0.f;
    float a3 = 0.f, k3 = 0.f, a4 = 0.f, k4 = 0.f;
    const float* xb = g_x4 + ((long long)b * 256) * NCELL + s;
    for (int ci = 0; ci < 256; ci++) {
        float v = xb[ci * NCELL];
        kadd(a0, k0, __fmul_rn(ws[0 * 256 + ci], v));
        kadd(a1, k1, __fmul_rn(ws[1 * 256 + ci], v));
        kadd(a2, k2, __fmul_rn(ws[2 * 256 + ci], v));
        kadd(a3, k3, __fmul_rn(ws[3 * 256 + ci], v));
        kadd(a4, k4, __fmul_rn(ws[4 * 256 + ci], v));
    }
    float* pb = g_pred + ((long long)b * 5) * NCELL + s;
    pb[0 * NCELL] = __fadd_rn(a0, bh[0]);
    pb[1 * NCELL] = __fadd_rn(a1, bh[1]);
    pb[2 * NCELL] = __fadd_rn(a2, bh[2]);
    pb[3 * NCELL] = __fadd_rn(a3, bh[3]);
    pb[4 * NCELL] = __fadd_rn(a4, bh[4]);
}

// ---------------------------------------------------------------------------
// Decode + top-200 (bitonic full sort: score desc, index asc — matches
// lax.top_k tie-break) + greedy NMS. One CTA of 1024 threads per batch.
// ---------------------------------------------------------------------------
__device__ __forceinline__ float sigmoid_d(float x) {
    return (float)(1.0 / (1.0 + exp(-(double)x)));
}

__global__ void decode_nms_kernel(float* __restrict__ out, int out_size) {
    const int b = blockIdx.x;
    const int t = threadIdx.x;

    __shared__ float sc[NCELL];
    __shared__ int   si[NCELL];
    __shared__ float bx1[TOPK], by1[TOPK], bx2[TOPK], by2[TOPK];
    __shared__ float bar[TOPK], bsv[TOPK];
    __shared__ int   keepS[TOPK];

    const float* pb = g_pred + (long long)b * 5 * NCELL;

    {
        float obj = sigmoid_d(pb[t]);
        sc[t] = (obj >= SCORE_T) ? obj : -1.0f;
        si[t] = t;
    }
    __syncthreads();

    for (int k = 2; k <= NCELL; k <<= 1) {
        for (int j = k >> 1; j > 0; j >>= 1) {
            int ixj = t ^ j;
            if (ixj > t) {
                float a = sc[t], c = sc[ixj];
                int   ia = si[t], ic = si[ixj];
                bool aAfter = (a < c) || (a == c && ia > ic);
                bool descRegion = ((t & k) == 0);
                if (descRegion ? aAfter : !aAfter) {
                    sc[t] = c;  sc[ixj] = a;
                    si[t] = ic; si[ixj] = ia;
                }
            }
            __syncthreads();
        }
    }

    if (t < TOPK) {
        int cell = si[t];
        float sval = sc[t];
        float p1 = pb[1 * NCELL + cell];
        float p2 = pb[2 * NCELL + cell];
        float p3 = pb[3 * NCELL + cell];
        float p4 = pb[4 * NCELL + cell];
        const float sx = 16.0f;
        const float sy = 16.0f;
        float txv = sigmoid_d(p1);
        float tyv = sigmoid_d(p2);
        float bw  = __fmul_rn((float)exp((double)p3), sx);
        float bh_ = __fmul_rn((float)exp((double)p4), sy);
        float gx = (float)(cell & (GRID - 1));
        float gy = (float)(cell >> 5);
        float cx = __fadd_rn(__fmul_rn(gx, sx), __fmul_rn(txv, sx));
        float cy = __fadd_rn(__fmul_rn(gy, sy), __fmul_rn(tyv, sy));
        float hw = __fmul_rn(bw, 0.5f);
        float hh = __fmul_rn(bh_, 0.5f);
        float x1 = fminf(fmaxf(__fsub_rn(cx, hw), 0.f), 511.0f);
        float y1 = fminf(fmaxf(__fsub_rn(cy, hh), 0.f), 511.0f);
        float x2 = fminf(fmaxf(__fadd_rn(cx, hw), 0.f), 511.0f);
        float y2 = fminf(fmaxf(__fadd_rn(cy, hh), 0.f), 511.0f);
        bx1[t] = x1; by1[t] = y1; bx2[t] = x2; by2[t] = y2;
        bar[t] = __fmul_rn(__fsub_rn(x2, x1), __fsub_rn(y2, y1));
        bsv[t] = sval;
        keepS[t] = (sval >= SCORE_T) ? 1 : 0;
    }

    for (int i = 0; i < TOPK; i++) {
        __syncthreads();
        if (keepS[i] && t > i && t < TOPK && keepS[t]) {
            float xx1 = fmaxf(bx1[i], bx1[t]);
            float yy1 = fmaxf(by1[i], by1[t]);
            float xx2 = fminf(bx2[i], bx2[t]);
            float yy2 = fminf(by2[i], by2[t]);
            float iw = fmaxf(__fsub_rn(xx2, xx1), 0.f);
            float ih = fmaxf(__fsub_rn(yy2, yy1), 0.f);
            float inter = __fmul_rn(iw, ih);
            float uni = __fsub_rn(__fadd_rn(bar[i], bar[t]), inter);
            float iou = __fdiv_rn(inter, fmaxf(uni, 1e-6f));
            if (iou > IOU_T) keepS[t] = 0;
        }
    }
    __syncthreads();

    if (t < TOPK) {
        float kf = keepS[t] ? 1.0f : 0.0f;
        float* o = out + ((long long)(b * TOPK + t)) * 5;
        o[0] = __fmul_rn(bx1[t], kf);
        o[1] = __fmul_rn(by1[t], kf);
        o[2] = __fmul_rn(bx2[t], kf);
        o[3] = __fmul_rn(by2[t], kf);
        o[4] = __fmul_rn(bsv[t], kf);
        if (out_size >= BB * TOPK * 5 + BB * TOPK) {
            out[BB * TOPK * 5 + b * TOPK + t] = kf;
        }
    }
}

// ---------------------------------------------------------------------------
// Host launch
// ---------------------------------------------------------------------------
extern "C" void kernel_launch(void* const* d_in, const int* in_sizes, int n_in,
                              void* d_out, int out_size) {
    const float* images = (const float*)d_in[0];
    const float* w1 = (const float*)d_in[1];
    const float* b1 = (const float*)d_in[2];
    const float* w2 = (const float*)d_in[3];
    const float* b2 = (const float*)d_in[4];
    const float* w3 = (const float*)d_in[5];
    const float* b3 = (const float*)d_in[6];
    const float* w4 = (const float*)d_in[7];
    const float* b4 = (const float*)d_in[8];
    const float* wh = (const float*)d_in[9];
    const float* bh = (const float*)d_in[10];

    float *x1p, *x2p, *x3p, *x4p;
    cudaGetSymbolAddress((void**)&x1p, g_x1);
    cudaGetSymbolAddress((void**)&x2p, g_x2);
    cudaGetSymbolAddress((void**)&x3p, g_x3);
    cudaGetSymbolAddress((void**)&x4p, g_x4);

    // L1: [8,3,512,512] -> [8,32,256,256]
    conv_relu_pool_t<3, 4, 3><<<dim3(16, 16, BB * (32 / 4)), 256>>>(
        images, w1, b1, x1p, 32, 512, 512);
    // L2: -> [8,64,128,128]
    conv_relu_pool_t<32, 4, 4><<<dim3(8, 8, BB * (64 / 4)), 256>>>(
        x1p, w2, b2, x2p, 64, 256, 256);
    // L3: -> [8,128,64,64]
    conv_relu_pool_t<64, 4, 4><<<dim3(4, 4, BB * (128 / 4)), 256>>>(
        x2p, w3, b3, x3p, 128, 128, 128);
    // L4: -> [8,256,32,32]
    conv_relu_pool_t<128, 4, 4><<<dim3(2, 2, BB * (256 / 4)), 256>>>(
        x3p, w4, b4, x4p, 256, 64, 64);
    // head 1x1
    head_kernel<<<(BB * NCELL + 255) / 256, 256>>>(wh, bh);
    // decode + topk + nms
    decode_nms_kernel<<<BB, NCELL>>>((float*)d_out, out_size);
}